// round 9
// baseline (speedup 1.0000x reference)
#include <cuda_runtime.h>
#include <cuda_bf16.h>

// Problem constants
#define B_  16
#define R_  64
#define S_  128
#define M_  64
#define L_  128
#define E_  4032            // R*R - R

// Output layout (float elements)
#define OFF_INC_ADD  0ull
#define OFF_INC_GAIN 131072ull
#define OFF_MEAN     262144ull
#define OFF_LOG      4456448ull
#define OFF_MSG      8650752ull

// Shared layout (floats)
#define XS_OFF    0            // xs[b][s] stride 132:  16*132 = 2112
#define H_OFF     2112         // 4 half-tile buffers x 4352 = 17408
#define HBUF      4352         // max(32*132, 64*68)
#define SMEAN_OFF 19520        // smean[b][m] stride 68: 1088
#define SADD_OFF  20608        // sadd[b][l] stride 132: 2112
#define SGAIN_OFF 22720        // sgain     stride 132: 2112
#define SMEM_FLOATS 24832      // 99328 bytes
#define XSS  132
#define W2S  132               // phase-2 weight row stride (128+4)
#define W3S  68                // phase-3 weight row stride (64+4)
#define SMS  68
#define SAS  132

typedef unsigned long long ull;

__device__ __forceinline__ ull fma2(ull a, ull b, ull c) {
    ull d;
    asm("fma.rn.f32x2 %0, %1, %2, %3;" : "=l"(d) : "l"(a), "l"(b), "l"(c));
    return d;
}
__device__ __forceinline__ void unpk(ull v, float& lo, float& hi) {
    asm("mov.b64 {%0, %1}, %2;" : "=f"(lo), "=f"(hi) : "l"(v));
}
__device__ __forceinline__ void red_add_v4(float* p, float4 v) {
    asm volatile("red.global.add.v4.f32 [%0], {%1, %2, %3, %4};"
                 :: "l"(p), "f"(v.x), "f"(v.y), "f"(v.z), "f"(v.w) : "memory");
}
__device__ __forceinline__ void cpa16(float* dst_smem, const float* src) {
    unsigned sa = (unsigned)__cvta_generic_to_shared(dst_smem);
    asm volatile("cp.async.cg.shared.global [%0], [%1], 16;" :: "r"(sa), "l"(src));
}
__device__ __forceinline__ void cp_commit() { asm volatile("cp.async.commit_group;"); }
__device__ __forceinline__ void cp_wait1()  { asm volatile("cp.async.wait_group 1;" ::: "memory"); }
__device__ __forceinline__ void cp_wait0()  { asm volatile("cp.async.wait_group 0;" ::: "memory"); }
__device__ __forceinline__ void bar_sync(int id, int cnt) {
    asm volatile("bar.sync %0, %1;" :: "r"(id), "r"(cnt) : "memory");
}
__device__ __forceinline__ void bar_arrive(int id, int cnt) {
    asm volatile("bar.arrive %0, %1;" :: "r"(id), "r"(cnt) : "memory");
}

// ---------------- init: zero inc regions + scat diagonals ----------------
__global__ void init_kernel(float* __restrict__ out) {
    int idx = blockIdx.x * blockDim.x + threadIdx.x;
    if (idx < 2 * B_ * R_ * L_) out[idx] = 0.0f;
    if (idx < 3 * B_ * R_ * M_) {
        int o  = idx / (B_ * R_ * M_);
        int r2 = idx % (B_ * R_ * M_);
        int b  = r2 / (R_ * M_);
        int rm = r2 % (R_ * M_);
        int r  = rm / M_;
        int m  = rm % M_;
        ull base = (o == 0) ? OFF_MEAN : ((o == 1) ? OFF_LOG : OFF_MSG);
        out[base + ((((ull)b * R_ + r) * R_ + r) * M_ + m)] = 0.0f;
    }
}

// ---------------- main: one block per edge, 4-stage half-tile pipeline ----
__global__ __launch_bounds__(256, 2) void edge_kernel(
    const float* __restrict__ source,
    const float* __restrict__ mean_w,
    const float* __restrict__ mean_b,
    const float* __restrict__ logstd_w,
    const float* __restrict__ logstd_b,
    const float* __restrict__ add_w,
    const float* __restrict__ gain_w,
    float* __restrict__ out)
{
    extern __shared__ float sm[];
    float* xs    = sm + XS_OFF;
    float* smean = sm + SMEAN_OFF;
    float* sadd  = sm + SADD_OFF;
    float* sgain = sm + SGAIN_OFF;

    const int e = blockIdx.x;
    const int s_idx = e / (R_ - 1);
    const int rem   = e % (R_ - 1);
    const int t_idx = rem + (rem >= s_idx ? 1 : 0);
    const int tid  = threadIdx.x;
    const bool isA = (tid < 128);
    const int  u   = tid & 127;
    const int  sub = isA ? 0 : 1;
    const int  barid = isA ? 1 : 2;
    float* H0 = sm + H_OFF + (sub * 2    ) * HBUF;
    float* H1 = sm + H_OFF + (sub * 2 + 1) * HBUF;

    const float* w2src = isA ? mean_w : logstd_w;
    const float* w3src = isA ? add_w  : gain_w;

    // ================= staging: xs + w2 halves ==============================
    #pragma unroll
    for (int k = 0; k < 2; k++) {
        int i = tid + k * 256;
        int b = i >> 5, c = i & 31;
        cpa16(xs + b * XSS + c * 4,
              source + (ull)b * (R_ * S_) + (ull)s_idx * S_ + c * 4);
    }
    #pragma unroll
    for (int k = 0; k < 8; k++) {                // w2 half0: rows 0..31
        int c = u + 128 * k;
        int row = c >> 5, col = c & 31;
        cpa16(H0 + row * W2S + col * 4,
              w2src + ((ull)e * M_ + row) * S_ + col * 4);
    }
    cp_commit();                                  // g0 = xs + w2a
    #pragma unroll
    for (int k = 0; k < 8; k++) {                // w2 half1: rows 32..63
        int c = u + 128 * k;
        int row = c >> 5, col = c & 31;
        cpa16(H1 + row * W2S + col * 4,
              w2src + ((ull)e * M_ + 32 + row) * S_ + col * 4);
    }
    cp_commit();                                  // g1 = w2b

    // bias prefetch: thread handles m = h*32 + 2*pr + r
    const int pr = u >> 3;                        // 0..15
    const int bq = u & 7;                         // 0..7
    const float* bsrc = isA ? mean_b : logstd_b;
    float bias[2][2];
    #pragma unroll
    for (int h = 0; h < 2; h++)
        #pragma unroll
        for (int r = 0; r < 2; r++)
            bias[h][r] = bsrc[(ull)e * M_ + h * 32 + 2 * pr + r];

    const ull cell = (ull)(s_idx * R_ + t_idx) * M_;

    cp_wait1();                                   // own g0
    __syncthreads();                              // xs + w2a complete (all)

    // ================= phase 2 halves =======================================
    #pragma unroll
    for (int h = 0; h < 2; h++) {
        float* W = h ? H1 : H0;
        const float* wr0 = W + (2 * pr) * W2S;
        const float* wr1 = W + (2 * pr + 1) * W2S;

        ull acc[2][2];
        #pragma unroll
        for (int r = 0; r < 2; r++)
            #pragma unroll
            for (int i = 0; i < 2; i++) acc[r][i] = 0ull;

        #pragma unroll 4
        for (int c = 0; c < 16; c++) {
            ulonglong2 wa0 = *reinterpret_cast<const ulonglong2*>(wr0 + 8 * c);
            ulonglong2 wb0 = *reinterpret_cast<const ulonglong2*>(wr0 + 8 * c + 4);
            ulonglong2 wa1 = *reinterpret_cast<const ulonglong2*>(wr1 + 8 * c);
            ulonglong2 wb1 = *reinterpret_cast<const ulonglong2*>(wr1 + 8 * c + 4);
            #pragma unroll
            for (int i = 0; i < 2; i++) {
                const int b = bq + 8 * i;
                const float* xr = xs + b * XSS + 8 * c;
                ulonglong2 xa = *reinterpret_cast<const ulonglong2*>(xr);
                ulonglong2 xb = *reinterpret_cast<const ulonglong2*>(xr + 4);
                acc[0][i] = fma2(xa.x, wa0.x, acc[0][i]);
                acc[0][i] = fma2(xa.y, wa0.y, acc[0][i]);
                acc[0][i] = fma2(xb.x, wb0.x, acc[0][i]);
                acc[0][i] = fma2(xb.y, wb0.y, acc[0][i]);
                acc[1][i] = fma2(xa.x, wa1.x, acc[1][i]);
                acc[1][i] = fma2(xa.y, wa1.y, acc[1][i]);
                acc[1][i] = fma2(xb.x, wb1.x, acc[1][i]);
                acc[1][i] = fma2(xb.y, wb1.y, acc[1][i]);
            }
        }

        // epilogue: smean (A) + direct global stores
        #pragma unroll
        for (int r = 0; r < 2; r++) {
            const int m = h * 32 + 2 * pr + r;
            #pragma unroll
            for (int i = 0; i < 2; i++) {
                const int b = bq + 8 * i;
                float lo, hi;
                unpk(acc[r][i], lo, hi);
                float v = lo + hi + bias[h][r];
                ull a = (ull)b * (R_ * R_ * M_) + cell + m;
                if (isA) {
                    smean[b * SMS + m] = v;
                    out[OFF_MEAN + a] = v;
                    out[OFF_MSG  + a] = v;
                } else {
                    out[OFF_LOG + a] = v;
                }
            }
        }

        if (h == 0) {
            bar_sync(barid, 128);                 // H0 free, all read done
            #pragma unroll
            for (int k = 0; k < 8; k++) {         // w3 half0 -> H0
                int c = u + 128 * k;
                int row = c >> 4, col = c & 15;
                cpa16(H0 + row * W3S + col * 4,
                      w3src + ((ull)e * L_ + row) * M_ + col * 4);
            }
            cp_commit();                          // g2 = w3a
            cp_wait1();                           // own g1 (w2b)
            bar_sync(barid, 128);                 // all g1 -> w2b ready
        }
    }

    bar_sync(barid, 128);                         // H1 free; phase2 complete
    if (isA) bar_arrive(3, 256);                  // publish smean

    #pragma unroll
    for (int k = 0; k < 8; k++) {                 // w3 half1 -> H1
        int c = u + 128 * k;
        int row = c >> 4, col = c & 15;
        cpa16(H1 + row * W3S + col * 4,
              w3src + ((ull)e * L_ + 64 + row) * M_ + col * 4);
    }
    cp_commit();                                  // g3 = w3b
    cp_wait1();                                   // own g2
    bar_sync(barid, 128);                         // all g2 -> w3a ready
    if (!isA) bar_sync(3, 256);                   // wait smean from SubA

    // ================= phase 3 halves =======================================
    const int lp  = u >> 2;                       // 0..31
    const int bq3 = u & 3;                        // 0..3
    float* sres = isA ? sadd : sgain;

    #pragma unroll
    for (int h = 0; h < 2; h++) {
        float* W = h ? H1 : H0;
        const float* wr0 = W + lp * W3S;          // local row lp
        const float* wr1 = W + (lp + 32) * W3S;   // local row lp+32

        ull acc[2][4];
        #pragma unroll
        for (int r = 0; r < 2; r++)
            #pragma unroll
            for (int i = 0; i < 4; i++) acc[r][i] = 0ull;

        #pragma unroll 4
        for (int c = 0; c < 8; c++) {
            ulonglong2 wa0 = *reinterpret_cast<const ulonglong2*>(wr0 + 8 * c);
            ulonglong2 wb0 = *reinterpret_cast<const ulonglong2*>(wr0 + 8 * c + 4);
            ulonglong2 wa1 = *reinterpret_cast<const ulonglong2*>(wr1 + 8 * c);
            ulonglong2 wb1 = *reinterpret_cast<const ulonglong2*>(wr1 + 8 * c + 4);
            #pragma unroll
            for (int i = 0; i < 4; i++) {
                const int b = bq3 + 4 * i;
                const float* mr = smean + b * SMS + 8 * c;
                ulonglong2 xa = *reinterpret_cast<const ulonglong2*>(mr);
                ulonglong2 xb = *reinterpret_cast<const ulonglong2*>(mr + 4);
                acc[0][i] = fma2(xa.x, wa0.x, acc[0][i]);
                acc[0][i] = fma2(xa.y, wa0.y, acc[0][i]);
                acc[0][i] = fma2(xb.x, wb0.x, acc[0][i]);
                acc[0][i] = fma2(xb.y, wb0.y, acc[0][i]);
                acc[1][i] = fma2(xa.x, wa1.x, acc[1][i]);
                acc[1][i] = fma2(xa.y, wa1.y, acc[1][i]);
                acc[1][i] = fma2(xb.x, wb1.x, acc[1][i]);
                acc[1][i] = fma2(xb.y, wb1.y, acc[1][i]);
            }
        }

        #pragma unroll
        for (int r = 0; r < 2; r++) {
            const int l = h * 64 + lp + 32 * r;
            #pragma unroll
            for (int i = 0; i < 4; i++) {
                const int b = bq3 + 4 * i;
                float lo, hi;
                unpk(acc[r][i], lo, hi);
                sres[b * SAS + l] = lo + hi;
            }
        }

        if (h == 0) {
            cp_wait0();                           // own g3
            bar_sync(barid, 128);                 // all g3 -> w3b ready
        }
    }
    bar_sync(barid, 128);                         // sadd/sgain visible

    // ================= phase 4: vectorized scatter-add ======================
    {
        const ull offI = isA ? OFF_INC_ADD : OFF_INC_GAIN;
        #pragma unroll
        for (int k = 0; k < 4; k++) {
            int i = u + 128 * k;
            int b = i >> 5;
            int q = i & 31;
            float4 v = *reinterpret_cast<const float4*>(sres + b * SAS + q * 4);
            float* dst = out + offI + (ull)(b * R_ + t_idx) * L_ + q * 4;
            red_add_v4(dst, v);
        }
    }
}

extern "C" void kernel_launch(void* const* d_in, const int* in_sizes, int n_in,
                              void* d_out, int out_size) {
    const float* source   = (const float*)d_in[0];
    const float* mean_w   = (const float*)d_in[1];
    const float* mean_b   = (const float*)d_in[2];
    const float* logstd_w = (const float*)d_in[3];
    const float* logstd_b = (const float*)d_in[4];
    const float* add_w    = (const float*)d_in[5];
    const float* gain_w   = (const float*)d_in[6];
    float* out = (float*)d_out;

    cudaFuncSetAttribute(edge_kernel, cudaFuncAttributeMaxDynamicSharedMemorySize,
                         SMEM_FLOATS * 4);

    init_kernel<<<(2 * B_ * R_ * L_ + 255) / 256, 256>>>(out);
    edge_kernel<<<E_, 256, SMEM_FLOATS * 4>>>(source, mean_w, mean_b,
                                              logstd_w, logstd_b,
                                              add_w, gain_w, out);
}

// round 12
// speedup vs baseline: 1.0875x; 1.0875x over previous
#include <cuda_runtime.h>
#include <cuda_bf16.h>

// Problem constants
#define B_  16
#define R_  64
#define S_  128
#define M_  64
#define L_  128
#define E_  4032            // R*R - R

// Output layout (float elements), 5 concatenated outputs:
#define OFF_INC_ADD  0ull
#define OFF_INC_GAIN 131072ull
#define OFF_MEAN     262144ull
#define OFF_LOG      4456448ull
#define OFF_MSG      8650752ull

// Shared layout (floats), total 24768 floats = 99072 B dynamic smem
#define XS_OFF    0            // xs[b][s]       16*128 = 2048
#define PA_OFF    2048         // SubA weights: 64*132=8448 (mean) / 128*68=8704 (add)
#define QB_OFF    10752        // SubB weights: logstd / gain (8704)
#define SMEAN_OFF 19456        // smean[b][m]   16*68 = 1088 -> ends 20544
#define SADD_OFF  20544        // sadd[b][l]    16*132 = 2112 -> ends 22656
#define SGAIN_OFF 22656        // sgain[b][l]   16*132 = 2112 -> ends 24768
#define SMEM_FLOATS 24768
#define W2S 132                // phase-2 weight row stride (128+4)
#define W3S 68                 // phase-3 weight row stride (64+4)
#define SMS 68
#define SAS 132

typedef unsigned long long ull;

// ---------------- packed f32x2 helpers ----------------
__device__ __forceinline__ ull fma2(ull a, ull b, ull c) {
    ull d;
    asm("fma.rn.f32x2 %0, %1, %2, %3;" : "=l"(d) : "l"(a), "l"(b), "l"(c));
    return d;
}
__device__ __forceinline__ void unpk(ull v, float& lo, float& hi) {
    asm("mov.b64 {%0, %1}, %2;" : "=f"(lo), "=f"(hi) : "l"(v));
}
__device__ __forceinline__ void red_add_v4(float* p, float4 v) {
    asm volatile("red.global.add.v4.f32 [%0], {%1, %2, %3, %4};"
                 :: "l"(p), "f"(v.x), "f"(v.y), "f"(v.z), "f"(v.w) : "memory");
}
__device__ __forceinline__ void cpa16(float* dst_smem, const float* src) {
    unsigned sa = (unsigned)__cvta_generic_to_shared(dst_smem);
    asm volatile("cp.async.cg.shared.global [%0], [%1], 16;" :: "r"(sa), "l"(src));
}
__device__ __forceinline__ void cp_commit() { asm volatile("cp.async.commit_group;"); }
__device__ __forceinline__ void cp_wait0()  { asm volatile("cp.async.wait_group 0;" ::: "memory"); }
__device__ __forceinline__ void bar_sync(int id, int cnt) {
    asm volatile("bar.sync %0, %1;" :: "r"(id), "r"(cnt) : "memory");
}
__device__ __forceinline__ void bar_arrive(int id, int cnt) {
    asm volatile("bar.arrive %0, %1;" :: "r"(id), "r"(cnt) : "memory");
}

// ---------------- init: zero inc regions + scat diagonals (vectorized) ----
__global__ void init_kernel(float* __restrict__ out) {
    int idx = blockIdx.x * blockDim.x + threadIdx.x;   // grid covers 65536
    // inc_add + inc_gain: 262144 floats = 65536 float4
    if (idx < 65536)
        reinterpret_cast<float4*>(out)[idx] = make_float4(0.f, 0.f, 0.f, 0.f);
    // diagonals: 3 * 16 * 64 rows of 64 floats = 49152 float4 chunks
    if (idx < 49152) {
        int o    = idx >> 14;              // 0..2
        int rest = idx & 16383;
        int b    = rest >> 10;             // 0..15
        int r    = (rest >> 4) & 63;       // 0..63
        int q    = rest & 15;              // 0..15
        ull base = (o == 0) ? OFF_MEAN : ((o == 1) ? OFF_LOG : OFF_MSG);
        ull a = base + (((ull)(b * R_ + r) * R_ + r) * M_) + q * 4;
        *reinterpret_cast<float4*>(out + a) = make_float4(0.f, 0.f, 0.f, 0.f);
    }
}

// ---------------- main: one block per edge, two 128-thread sub-pipelines ----
__global__ __launch_bounds__(256, 2) void edge_kernel(
    const float* __restrict__ source,
    const float* __restrict__ mean_w,
    const float* __restrict__ mean_b,
    const float* __restrict__ logstd_w,
    const float* __restrict__ logstd_b,
    const float* __restrict__ add_w,
    const float* __restrict__ gain_w,
    float* __restrict__ out)
{
    extern __shared__ float sm[];
    float* xs    = sm + XS_OFF;      // [b][s] stride 128 (warp-broadcast reads)
    float* smean = sm + SMEAN_OFF;   // [b][m] stride 68
    float* sadd  = sm + SADD_OFF;    // [b][l] stride 132
    float* sgain = sm + SGAIN_OFF;

    const int e = blockIdx.x;
    const int s_idx = e / (R_ - 1);
    const int rem   = e % (R_ - 1);
    const int t_idx = rem + (rem >= s_idx ? 1 : 0);
    const int tid = threadIdx.x;
    const bool isA = (tid < 128);
    const int  u   = tid & 127;
    float* WB = sm + (isA ? PA_OFF : QB_OFF);

    // ---- staging 1: xs (all threads) + phase-2 weights (per sub) ----
    #pragma unroll
    for (int k = 0; k < 2; k++) {
        int i = tid + k * 256;
        int b = i >> 5, c = i & 31;
        cpa16(xs + 4 * i,
              source + (ull)b * (R_ * S_) + (ull)s_idx * S_ + c * 4);
    }
    {
        const float* w2src = isA ? mean_w : logstd_w;
        #pragma unroll
        for (int k = 0; k < 16; k++) {
            int c   = u + k * 128;
            int row = c >> 5;
            int col = c & 31;
            cpa16(WB + row * W2S + col * 4,
                  w2src + ((ull)e * M_ + row) * S_ + col * 4);
        }
    }
    cp_commit();
    cp_wait0();
    __syncthreads();

    // ---- phase 2: 2 adjacent rows/thread (mg2, mg2+1), 4 batches/thread ----
    {
        const int warpu = u >> 5;           // 0..3 -> batch quad
        const int mg2   = (u & 31) * 2;     // even row
        const int b0    = warpu * 4;

        const float* w0 = WB + mg2 * W2S;
        const float* w1 = WB + (mg2 + 1) * W2S;
        const float* bsrc = isA ? mean_b : logstd_b;
        const float bias0 = bsrc[e * M_ + mg2];
        const float bias1 = bsrc[e * M_ + mg2 + 1];

        ull acc[2][4];
        #pragma unroll
        for (int r = 0; r < 2; r++)
            #pragma unroll
            for (int b = 0; b < 4; b++) acc[r][b] = 0ull;

        #pragma unroll 4
        for (int c = 0; c < 16; c++) {      // 8 s per chunk
            const int s0 = c * 8;
            ulonglong2 wa0 = *reinterpret_cast<const ulonglong2*>(w0 + s0);
            ulonglong2 wb0 = *reinterpret_cast<const ulonglong2*>(w0 + s0 + 4);
            ulonglong2 wa1 = *reinterpret_cast<const ulonglong2*>(w1 + s0);
            ulonglong2 wb1 = *reinterpret_cast<const ulonglong2*>(w1 + s0 + 4);
            #pragma unroll
            for (int b = 0; b < 4; b++) {
                const float* xr = xs + (b0 + b) * S_ + s0;   // warp-broadcast
                ulonglong2 xa = *reinterpret_cast<const ulonglong2*>(xr);
                ulonglong2 xb = *reinterpret_cast<const ulonglong2*>(xr + 4);
                acc[0][b] = fma2(xa.x, wa0.x, acc[0][b]);
                acc[0][b] = fma2(xa.y, wa0.y, acc[0][b]);
                acc[0][b] = fma2(xb.x, wb0.x, acc[0][b]);
                acc[0][b] = fma2(xb.y, wb0.y, acc[0][b]);
                acc[1][b] = fma2(xa.x, wa1.x, acc[1][b]);
                acc[1][b] = fma2(xa.y, wa1.y, acc[1][b]);
                acc[1][b] = fma2(xb.x, wb1.x, acc[1][b]);
                acc[1][b] = fma2(xb.y, wb1.y, acc[1][b]);
            }
        }

        const ull cellb = (ull)(s_idx * R_ + t_idx) * M_ + mg2;
        #pragma unroll
        for (int b = 0; b < 4; b++) {
            float lo0, hi0, lo1, hi1;
            unpk(acc[0][b], lo0, hi0);
            unpk(acc[1][b], lo1, hi1);
            float2 v = make_float2(lo0 + hi0 + bias0, lo1 + hi1 + bias1);
            ull a = (ull)(b0 + b) * (R_ * R_ * M_) + cellb;
            if (isA) {
                *reinterpret_cast<float2*>(smean + (b0 + b) * SMS + mg2) = v;
                *reinterpret_cast<float2*>(out + OFF_MEAN + a) = v;
                *reinterpret_cast<float2*>(out + OFF_MSG  + a) = v;   // msg == mean
            } else {
                *reinterpret_cast<float2*>(out + OFF_LOG + a) = v;
            }
        }
    }

    // ---- sub barriers: free own weight buffer; publish smean (A -> B) ----
    if (isA) { bar_sync(1, 128); bar_arrive(3, 256); }
    else     { bar_sync(2, 128); }

    // ---- staging 2: phase-3 weights (per sub) ----
    {
        const float* w3src = isA ? add_w : gain_w;
        #pragma unroll
        for (int k = 0; k < 16; k++) {
            int c   = u + k * 128;
            int row = c >> 4;
            int col = c & 15;
            cpa16(WB + row * W3S + col * 4,
                  w3src + ((ull)e * L_ + row) * M_ + col * 4);
        }
    }
    cp_commit();
    cp_wait0();
    if (isA) { bar_sync(1, 128); }
    else     { bar_sync(2, 128); bar_sync(3, 256); }  // wait smean from SubA

    // ---- phase 3: 4 rows/thread (lp+32r), 4 batches/thread (bq3+4i) ----
    {
        const int lp  = u >> 2;             // 0..31
        const int bq3 = u & 3;              // 0..3

        ull acc[4][4];
        #pragma unroll
        for (int r = 0; r < 4; r++)
            #pragma unroll
            for (int i = 0; i < 4; i++) acc[r][i] = 0ull;

        #pragma unroll 2
        for (int c = 0; c < 8; c++) {       // 8 m per chunk
            const int m0 = c * 8;
            ulonglong2 wa[4], wb[4];
            #pragma unroll
            for (int r = 0; r < 4; r++) {
                const float* wr = WB + (lp + 32 * r) * W3S + m0;
                wa[r] = *reinterpret_cast<const ulonglong2*>(wr);
                wb[r] = *reinterpret_cast<const ulonglong2*>(wr + 4);
            }
            #pragma unroll
            for (int i = 0; i < 4; i++) {
                const int b = bq3 + 4 * i;
                const float* mr = smean + b * SMS + m0;
                ulonglong2 xa = *reinterpret_cast<const ulonglong2*>(mr);
                ulonglong2 xb = *reinterpret_cast<const ulonglong2*>(mr + 4);
                #pragma unroll
                for (int r = 0; r < 4; r++) {
                    acc[r][i] = fma2(xa.x, wa[r].x, acc[r][i]);
                    acc[r][i] = fma2(xa.y, wa[r].y, acc[r][i]);
                    acc[r][i] = fma2(xb.x, wb[r].x, acc[r][i]);
                    acc[r][i] = fma2(xb.y, wb[r].y, acc[r][i]);
                }
            }
        }

        float* sres = isA ? sadd : sgain;
        #pragma unroll
        for (int r = 0; r < 4; r++) {
            const int l = lp + 32 * r;
            #pragma unroll
            for (int i = 0; i < 4; i++) {
                const int b = bq3 + 4 * i;
                float lo, hi;
                unpk(acc[r][i], lo, hi);
                sres[b * SAS + l] = lo + hi;
            }
        }
    }
    if (isA) bar_sync(1, 128);
    else     bar_sync(2, 128);

    // ---- phase 4: vectorized scatter-add (each sub reduces its own array) ----
    {
        float* sres = isA ? sadd : sgain;
        const ull offI = isA ? OFF_INC_ADD : OFF_INC_GAIN;
        #pragma unroll
        for (int k = 0; k < 4; k++) {
            int i = u + 128 * k;
            int b = i >> 5;
            int q = i & 31;
            float4 v = *reinterpret_cast<const float4*>(sres + b * SAS + q * 4);
            float* dst = out + offI + (ull)(b * R_ + t_idx) * L_ + q * 4;
            red_add_v4(dst, v);
        }
    }
}

extern "C" void kernel_launch(void* const* d_in, const int* in_sizes, int n_in,
                              void* d_out, int out_size) {
    const float* source   = (const float*)d_in[0];
    const float* mean_w   = (const float*)d_in[1];
    const float* mean_b   = (const float*)d_in[2];
    const float* logstd_w = (const float*)d_in[3];
    const float* logstd_b = (const float*)d_in[4];
    const float* add_w    = (const float*)d_in[5];
    const float* gain_w   = (const float*)d_in[6];
    float* out = (float*)d_out;

    cudaFuncSetAttribute(edge_kernel, cudaFuncAttributeMaxDynamicSharedMemorySize,
                         SMEM_FLOATS * 4);

    init_kernel<<<256, 256>>>(out);
    edge_kernel<<<E_, 256, SMEM_FLOATS * 4>>>(source, mean_w, mean_b,
                                              logstd_w, logstd_b,
                                              add_w, gain_w, out);
}

// round 13
// speedup vs baseline: 1.2188x; 1.1207x over previous
#include <cuda_runtime.h>
#include <cuda_bf16.h>

// Problem constants
#define B_  16
#define R_  64
#define S_  128
#define M_  64
#define L_  128
#define E_  4032            // R*R - R

// Output layout (float elements), 5 concatenated outputs:
#define OFF_INC_ADD  0ull
#define OFF_INC_GAIN 131072ull
#define OFF_MEAN     262144ull
#define OFF_LOG      4456448ull
#define OFF_MSG      8650752ull

// Shared layout (floats), total 28672 floats = 114688 B dynamic smem
#define XS_OFF    0            // xs[b][s]       16*128 = 2048
#define PA_OFF    2048         // SubA WB: w2 (64*132=8448) / w3-late rows 64-127 (64*68=4352)
#define QB_OFF    10496        // SubB WB
#define P3A_OFF   18944        // SubA w3-early rows 0-63: 64*68 = 4352
#define P3B_OFF   23296        // SubB w3-early
#define SMEAN_OFF 27648        // smean[b][m] stride 64: 1024 -> ends 28672
#define SMEM_FLOATS 28672
#define W2S 132                // phase-2 weight row stride (128+4)
#define W3S 68                 // phase-3 weight row stride (64+4)

typedef unsigned long long ull;

// ---------------- packed f32x2 helpers ----------------
__device__ __forceinline__ ull fma2(ull a, ull b, ull c) {
    ull d;
    asm("fma.rn.f32x2 %0, %1, %2, %3;" : "=l"(d) : "l"(a), "l"(b), "l"(c));
    return d;
}
__device__ __forceinline__ void unpk(ull v, float& lo, float& hi) {
    asm("mov.b64 {%0, %1}, %2;" : "=f"(lo), "=f"(hi) : "l"(v));
}
__device__ __forceinline__ void red_add_f32(float* p, float v) {
    asm volatile("red.global.add.f32 [%0], %1;" :: "l"(p), "f"(v) : "memory");
}
__device__ __forceinline__ void cpa16(float* dst_smem, const float* src) {
    unsigned sa = (unsigned)__cvta_generic_to_shared(dst_smem);
    asm volatile("cp.async.cg.shared.global [%0], [%1], 16;" :: "r"(sa), "l"(src));
}
__device__ __forceinline__ void cp_commit() { asm volatile("cp.async.commit_group;"); }
__device__ __forceinline__ void cp_wait1()  { asm volatile("cp.async.wait_group 1;" ::: "memory"); }
__device__ __forceinline__ void cp_wait0()  { asm volatile("cp.async.wait_group 0;" ::: "memory"); }
__device__ __forceinline__ void bar_sync(int id, int cnt) {
    asm volatile("bar.sync %0, %1;" :: "r"(id), "r"(cnt) : "memory");
}
__device__ __forceinline__ void bar_arrive(int id, int cnt) {
    asm volatile("bar.arrive %0, %1;" :: "r"(id), "r"(cnt) : "memory");
}

// ---------------- init: zero inc regions + scat diagonals (vectorized) ----
__global__ void init_kernel(float* __restrict__ out) {
    int idx = blockIdx.x * blockDim.x + threadIdx.x;   // grid covers 65536
    if (idx < 65536)
        reinterpret_cast<float4*>(out)[idx] = make_float4(0.f, 0.f, 0.f, 0.f);
    if (idx < 49152) {
        int o    = idx >> 14;              // 0..2
        int rest = idx & 16383;
        int b    = rest >> 10;             // 0..15
        int r    = (rest >> 4) & 63;       // 0..63
        int q    = rest & 15;              // 0..15
        ull base = (o == 0) ? OFF_MEAN : ((o == 1) ? OFF_LOG : OFF_MSG);
        ull a = base + (((ull)(b * R_ + r) * R_ + r) * M_) + q * 4;
        *reinterpret_cast<float4*>(out + a) = make_float4(0.f, 0.f, 0.f, 0.f);
    }
}

// ---------------- main: one block per edge, two 128-thread sub-pipelines ----
__global__ __launch_bounds__(256, 2) void edge_kernel(
    const float* __restrict__ source,
    const float* __restrict__ mean_w,
    const float* __restrict__ mean_b,
    const float* __restrict__ logstd_w,
    const float* __restrict__ logstd_b,
    const float* __restrict__ add_w,
    const float* __restrict__ gain_w,
    float* __restrict__ out)
{
    extern __shared__ float sm[];
    float* xs    = sm + XS_OFF;      // [b][s] stride 128 (warp-broadcast reads)
    float* smean = sm + SMEAN_OFF;   // [b][m] stride 64 (broadcast reads, cf-writes)

    const int e = blockIdx.x;
    const int s_idx = e / (R_ - 1);
    const int rem   = e % (R_ - 1);
    const int t_idx = rem + (rem >= s_idx ? 1 : 0);
    const int tid = threadIdx.x;
    const bool isA = (tid < 128);
    const int  u   = tid & 127;
    float* WB = sm + (isA ? PA_OFF  : QB_OFF);    // w2 now, w3 rows 64-127 later
    float* P3 = sm + (isA ? P3A_OFF : P3B_OFF);   // w3 rows 0-63 (prefetched)

    // ---- staging g0: xs (all threads) + phase-2 weights (per sub) ----
    #pragma unroll
    for (int k = 0; k < 2; k++) {
        int i = tid + k * 256;
        int b = i >> 5, c = i & 31;
        cpa16(xs + 4 * i,
              source + (ull)b * (R_ * S_) + (ull)s_idx * S_ + c * 4);
    }
    {
        const float* w2src = isA ? mean_w : logstd_w;
        #pragma unroll
        for (int k = 0; k < 16; k++) {
            int c   = u + k * 128;
            int row = c >> 5;
            int col = c & 31;
            cpa16(WB + row * W2S + col * 4,
                  w2src + ((ull)e * M_ + row) * S_ + col * 4);
        }
    }
    cp_commit();                                  // g0 = xs + w2

    // ---- staging g1: w3-early rows 0-63 -> P3 (lands during phase 2) ----
    {
        const float* w3src = isA ? add_w : gain_w;
        #pragma unroll
        for (int k = 0; k < 8; k++) {
            int c   = u + k * 128;
            int row = c >> 4;                     // 0..63
            int col = c & 15;
            cpa16(P3 + row * W3S + col * 4,
                  w3src + ((ull)e * L_ + row) * M_ + col * 4);
        }
    }
    cp_commit();                                  // g1 = w3-early

    cp_wait1();                                   // g0 done (g1 may be pending)
    __syncthreads();                              // xs + all w2 visible

    // ---- phase 2: 2 rows/thread (mg, mg+32), 4 batches/thread  [= R7] ----
    {
        const int warpu = u >> 5;           // 0..3 -> batch quad
        const int mg    = u & 31;
        const int b0    = warpu * 4;

        const float* w0 = WB + mg * W2S;
        const float* w1 = WB + (mg + 32) * W2S;
        const float* bsrc = isA ? mean_b : logstd_b;
        const float bias0 = bsrc[(ull)e * M_ + mg];
        const float bias1 = bsrc[(ull)e * M_ + mg + 32];

        ull acc[2][4];
        #pragma unroll
        for (int r = 0; r < 2; r++)
            #pragma unroll
            for (int b = 0; b < 4; b++) acc[r][b] = 0ull;

        #pragma unroll 4
        for (int c = 0; c < 16; c++) {      // 8 s per chunk
            const int s0 = c * 8;
            ulonglong2 wa0 = *reinterpret_cast<const ulonglong2*>(w0 + s0);
            ulonglong2 wb0 = *reinterpret_cast<const ulonglong2*>(w0 + s0 + 4);
            ulonglong2 wa1 = *reinterpret_cast<const ulonglong2*>(w1 + s0);
            ulonglong2 wb1 = *reinterpret_cast<const ulonglong2*>(w1 + s0 + 4);
            #pragma unroll
            for (int b = 0; b < 4; b++) {
                const float* xr = xs + (b0 + b) * S_ + s0;   // warp-broadcast
                ulonglong2 xa = *reinterpret_cast<const ulonglong2*>(xr);
                ulonglong2 xb = *reinterpret_cast<const ulonglong2*>(xr + 4);
                acc[0][b] = fma2(xa.x, wa0.x, acc[0][b]);
                acc[0][b] = fma2(xa.y, wa0.y, acc[0][b]);
                acc[0][b] = fma2(xb.x, wb0.x, acc[0][b]);
                acc[0][b] = fma2(xb.y, wb0.y, acc[0][b]);
                acc[1][b] = fma2(xa.x, wa1.x, acc[1][b]);
                acc[1][b] = fma2(xa.y, wa1.y, acc[1][b]);
                acc[1][b] = fma2(xb.x, wb1.x, acc[1][b]);
                acc[1][b] = fma2(xb.y, wb1.y, acc[1][b]);
            }
        }

        const ull cellb = (ull)(s_idx * R_ + t_idx) * M_;
        #pragma unroll
        for (int r = 0; r < 2; r++) {
            const int m = mg + 32 * r;
            const float bias = r ? bias1 : bias0;
            #pragma unroll
            for (int b = 0; b < 4; b++) {
                float lo, hi;
                unpk(acc[r][b], lo, hi);
                float v = lo + hi + bias;
                ull a = (ull)(b0 + b) * (R_ * R_ * M_) + cellb + m;
                if (isA) {
                    smean[(b0 + b) * M_ + m] = v;
                    out[OFF_MEAN + a] = v;
                    out[OFF_MSG  + a] = v;          // msg == mean
                } else {
                    out[OFF_LOG + a] = v;
                }
            }
        }
    }

    // ---- sub barriers: free own WB; publish smean (A -> B) ----
    if (isA) { bar_sync(1, 128); bar_arrive(3, 256); }
    else     { bar_sync(2, 128); }

    // ---- staging g2: w3-late rows 64-127 -> WB (lands during pass A) ----
    {
        const float* w3src = isA ? add_w : gain_w;
        #pragma unroll
        for (int k = 0; k < 8; k++) {
            int c   = u + k * 128;
            int row = c >> 4;                     // local 0..63 -> global 64+row
            int col = c & 15;
            cpa16(WB + row * W3S + col * 4,
                  w3src + ((ull)e * L_ + 64 + row) * M_ + col * 4);
        }
    }
    cp_commit();                                  // g2 = w3-late

    cp_wait1();                                   // own g1 (w3-early) done
    if (isA) { bar_sync(1, 128); }                // all sub's g1 done
    else     { bar_sync(2, 128); bar_sync(3, 256); }  // + smean from SubA

    // ---- phase 3: two single-row passes, 8 batches each  [R7 mapping] ----
    const int bs = u >> 6;                        // 0/1 -> batch octet
    const int lg = u & 63;                        // lanes consecutive within warp
    const int b0 = bs * 8;
    const ull offI = isA ? OFF_INC_ADD : OFF_INC_GAIN;

    // pass A: row lg (from P3)
    {
        const float* wr = P3 + lg * W3S;
        ull acc[8];
        #pragma unroll
        for (int i = 0; i < 8; i++) acc[i] = 0ull;

        #pragma unroll 2
        for (int c = 0; c < 8; c++) {             // 8 m per chunk
            ulonglong2 wa = *reinterpret_cast<const ulonglong2*>(wr + 8 * c);
            ulonglong2 wb = *reinterpret_cast<const ulonglong2*>(wr + 8 * c + 4);
            #pragma unroll
            for (int i = 0; i < 8; i++) {
                const float* mr = smean + (b0 + i) * M_ + 8 * c;   // broadcast
                ulonglong2 xa = *reinterpret_cast<const ulonglong2*>(mr);
                ulonglong2 xb = *reinterpret_cast<const ulonglong2*>(mr + 4);
                acc[i] = fma2(xa.x, wa.x, acc[i]);
                acc[i] = fma2(xa.y, wa.y, acc[i]);
                acc[i] = fma2(xb.x, wb.x, acc[i]);
                acc[i] = fma2(xb.y, wb.y, acc[i]);
            }
        }
        #pragma unroll
        for (int i = 0; i < 8; i++) {
            float lo, hi;
            unpk(acc[i], lo, hi);
            red_add_f32(out + offI + (ull)((b0 + i) * R_ + t_idx) * L_ + lg,
                        lo + hi);
        }
    }

    cp_wait0();                                   // own g2 done
    if (isA) bar_sync(1, 128);                    // all sub's g2 done
    else     bar_sync(2, 128);

    // pass B: row lg + 64 (from WB, local index lg)
    {
        const float* wr = WB + lg * W3S;
        ull acc[8];
        #pragma unroll
        for (int i = 0; i < 8; i++) acc[i] = 0ull;

        #pragma unroll 2
        for (int c = 0; c < 8; c++) {
            ulonglong2 wa = *reinterpret_cast<const ulonglong2*>(wr + 8 * c);
            ulonglong2 wb = *reinterpret_cast<const ulonglong2*>(wr + 8 * c + 4);
            #pragma unroll
            for (int i = 0; i < 8; i++) {
                const float* mr = smean + (b0 + i) * M_ + 8 * c;   // broadcast
                ulonglong2 xa = *reinterpret_cast<const ulonglong2*>(mr);
                ulonglong2 xb = *reinterpret_cast<const ulonglong2*>(mr + 4);
                acc[i] = fma2(xa.x, wa.x, acc[i]);
                acc[i] = fma2(xa.y, wa.y, acc[i]);
                acc[i] = fma2(xb.x, wb.x, acc[i]);
                acc[i] = fma2(xb.y, wb.y, acc[i]);
            }
        }
        #pragma unroll
        for (int i = 0; i < 8; i++) {
            float lo, hi;
            unpk(acc[i], lo, hi);
            red_add_f32(out + offI + (ull)((b0 + i) * R_ + t_idx) * L_ + lg + 64,
                        lo + hi);
        }
    }
}

extern "C" void kernel_launch(void* const* d_in, const int* in_sizes, int n_in,
                              void* d_out, int out_size) {
    const float* source   = (const float*)d_in[0];
    const float* mean_w   = (const float*)d_in[1];
    const float* mean_b   = (const float*)d_in[2];
    const float* logstd_w = (const float*)d_in[3];
    const float* logstd_b = (const float*)d_in[4];
    const float* add_w    = (const float*)d_in[5];
    const float* gain_w   = (const float*)d_in[6];
    float* out = (float*)d_out;

    cudaFuncSetAttribute(edge_kernel, cudaFuncAttributeMaxDynamicSharedMemorySize,
                         SMEM_FLOATS * 4);

    init_kernel<<<256, 256>>>(out);
    edge_kernel<<<E_, 256, SMEM_FLOATS * 4>>>(source, mean_w, mean_b,
                                              logstd_w, logstd_b,
                                              add_w, gain_w, out);
}

// round 14
// speedup vs baseline: 1.3265x; 1.0883x over previous
#include <cuda_runtime.h>
#include <cuda_bf16.h>

// Problem constants
#define B_  16
#define R_  64
#define S_  128
#define M_  64
#define L_  128
#define E_  4032            // R*R - R

// Output layout (float elements), 5 concatenated outputs:
#define OFF_INC_ADD  0ull
#define OFF_INC_GAIN 131072ull
#define OFF_MEAN     262144ull
#define OFF_LOG      4456448ull
#define OFF_MSG      8650752ull

// Shared layout (floats), total 24768 floats = 99072 B dynamic smem
#define XS_OFF    0            // xs[b][s]       16*128 = 2048
#define PA_OFF    2048         // SubA weights: w2 64*132=8448 / w3 128*68=8704
#define QB_OFF    10752        // SubB weights
#define SMEAN_OFF 19456        // smean[b][m] stride 68: 1088 -> ends 20544
#define SADD_OFF  20544        // sadd[b][l]  stride 132: 2112 -> ends 22656
#define SGAIN_OFF 22656        // sgain[b][l] stride 132: 2112 -> ends 24768
#define SMEM_FLOATS 24768
#define W2S 132                // phase-2 weight row stride (128+4)
#define W3S 68                 // phase-3 weight row stride (64+4)
#define SMS 68                 // smean row stride
#define SAS 132                // sadd/sgain row stride

typedef unsigned long long ull;

// ---------------- packed f32x2 helpers ----------------
__device__ __forceinline__ ull fma2(ull a, ull b, ull c) {
    ull d;
    asm("fma.rn.f32x2 %0, %1, %2, %3;" : "=l"(d) : "l"(a), "l"(b), "l"(c));
    return d;
}
__device__ __forceinline__ void unpk(ull v, float& lo, float& hi) {
    asm("mov.b64 {%0, %1}, %2;" : "=f"(lo), "=f"(hi) : "l"(v));
}
__device__ __forceinline__ void red_add_v4(float* p, float4 v) {
    asm volatile("red.global.add.v4.f32 [%0], {%1, %2, %3, %4};"
                 :: "l"(p), "f"(v.x), "f"(v.y), "f"(v.z), "f"(v.w) : "memory");
}
__device__ __forceinline__ void cpa16(float* dst_smem, const float* src) {
    unsigned sa = (unsigned)__cvta_generic_to_shared(dst_smem);
    asm volatile("cp.async.cg.shared.global [%0], [%1], 16;" :: "r"(sa), "l"(src));
}
__device__ __forceinline__ void cp_commit() { asm volatile("cp.async.commit_group;"); }
__device__ __forceinline__ void cp_wait0()  { asm volatile("cp.async.wait_group 0;" ::: "memory"); }
__device__ __forceinline__ void bar_sync(int id, int cnt) {
    asm volatile("bar.sync %0, %1;" :: "r"(id), "r"(cnt) : "memory");
}
__device__ __forceinline__ void bar_arrive(int id, int cnt) {
    asm volatile("bar.arrive %0, %1;" :: "r"(id), "r"(cnt) : "memory");
}

// ---------------- init: zero inc regions + scat diagonals (vectorized) ----
__global__ void init_kernel(float* __restrict__ out) {
    int idx = blockIdx.x * blockDim.x + threadIdx.x;   // grid covers 65536
    if (idx < 65536)
        reinterpret_cast<float4*>(out)[idx] = make_float4(0.f, 0.f, 0.f, 0.f);
    if (idx < 49152) {
        int o    = idx >> 14;              // 0..2
        int rest = idx & 16383;
        int b    = rest >> 10;             // 0..15
        int r    = (rest >> 4) & 63;       // 0..63
        int q    = rest & 15;              // 0..15
        ull base = (o == 0) ? OFF_MEAN : ((o == 1) ? OFF_LOG : OFF_MSG);
        ull a = base + (((ull)(b * R_ + r) * R_ + r) * M_) + q * 4;
        *reinterpret_cast<float4*>(out + a) = make_float4(0.f, 0.f, 0.f, 0.f);
    }
}

// ---------------- main: one block per edge, two 128-thread sub-pipelines ----
__global__ __launch_bounds__(256, 2) void edge_kernel(
    const float* __restrict__ source,
    const float* __restrict__ mean_w,
    const float* __restrict__ mean_b,
    const float* __restrict__ logstd_w,
    const float* __restrict__ logstd_b,
    const float* __restrict__ add_w,
    const float* __restrict__ gain_w,
    float* __restrict__ out)
{
    extern __shared__ float sm[];
    float* xs    = sm + XS_OFF;      // [b][s] stride 128 (warp-broadcast reads)
    float* smean = sm + SMEAN_OFF;   // [b][m] stride 68
    float* sadd  = sm + SADD_OFF;    // [b][l] stride 132
    float* sgain = sm + SGAIN_OFF;

    const int e = blockIdx.x;
    const int s_idx = e / (R_ - 1);
    const int rem   = e % (R_ - 1);
    const int t_idx = rem + (rem >= s_idx ? 1 : 0);
    const int tid = threadIdx.x;
    const bool isA = (tid < 128);
    const int  u   = tid & 127;
    float* WB = sm + (isA ? PA_OFF : QB_OFF);

    // ---- staging 1: xs (all threads) + phase-2 weights (per sub) ----
    #pragma unroll
    for (int k = 0; k < 2; k++) {
        int i = tid + k * 256;
        int b = i >> 5, c = i & 31;
        cpa16(xs + 4 * i,
              source + (ull)b * (R_ * S_) + (ull)s_idx * S_ + c * 4);
    }
    {
        const float* w2src = isA ? mean_w : logstd_w;
        #pragma unroll
        for (int k = 0; k < 16; k++) {
            int c   = u + k * 128;
            int row = c >> 5;
            int col = c & 31;
            cpa16(WB + row * W2S + col * 4,
                  w2src + ((ull)e * M_ + row) * S_ + col * 4);
        }
    }
    cp_commit();
    cp_wait0();
    __syncthreads();

    // ---- phase 2: 2 rows/thread (mg, mg+32), 4 batches/thread  [= R7] ----
    {
        const int warpu = u >> 5;           // 0..3 -> batch quad
        const int mg    = u & 31;
        const int b0    = warpu * 4;

        const float* w0 = WB + mg * W2S;
        const float* w1 = WB + (mg + 32) * W2S;
        const float* bsrc = isA ? mean_b : logstd_b;
        const float bias0 = bsrc[(ull)e * M_ + mg];
        const float bias1 = bsrc[(ull)e * M_ + mg + 32];

        ull acc[2][4];
        #pragma unroll
        for (int r = 0; r < 2; r++)
            #pragma unroll
            for (int b = 0; b < 4; b++) acc[r][b] = 0ull;

        #pragma unroll 4
        for (int c = 0; c < 16; c++) {      // 8 s per chunk
            const int s0 = c * 8;
            ulonglong2 wa0 = *reinterpret_cast<const ulonglong2*>(w0 + s0);
            ulonglong2 wb0 = *reinterpret_cast<const ulonglong2*>(w0 + s0 + 4);
            ulonglong2 wa1 = *reinterpret_cast<const ulonglong2*>(w1 + s0);
            ulonglong2 wb1 = *reinterpret_cast<const ulonglong2*>(w1 + s0 + 4);
            #pragma unroll
            for (int b = 0; b < 4; b++) {
                const float* xr = xs + (b0 + b) * S_ + s0;   // warp-broadcast
                ulonglong2 xa = *reinterpret_cast<const ulonglong2*>(xr);
                ulonglong2 xb = *reinterpret_cast<const ulonglong2*>(xr + 4);
                acc[0][b] = fma2(xa.x, wa0.x, acc[0][b]);
                acc[0][b] = fma2(xa.y, wa0.y, acc[0][b]);
                acc[0][b] = fma2(xb.x, wb0.x, acc[0][b]);
                acc[0][b] = fma2(xb.y, wb0.y, acc[0][b]);
                acc[1][b] = fma2(xa.x, wa1.x, acc[1][b]);
                acc[1][b] = fma2(xa.y, wa1.y, acc[1][b]);
                acc[1][b] = fma2(xb.x, wb1.x, acc[1][b]);
                acc[1][b] = fma2(xb.y, wb1.y, acc[1][b]);
            }
        }

        const ull cellb = (ull)(s_idx * R_ + t_idx) * M_;
        #pragma unroll
        for (int r = 0; r < 2; r++) {
            const int m = mg + 32 * r;
            const float bias = r ? bias1 : bias0;
            #pragma unroll
            for (int b = 0; b < 4; b++) {
                float lo, hi;
                unpk(acc[r][b], lo, hi);
                float v = lo + hi + bias;
                ull a = (ull)(b0 + b) * (R_ * R_ * M_) + cellb + m;
                if (isA) {
                    smean[(b0 + b) * SMS + m] = v;
                    out[OFF_MEAN + a] = v;
                    out[OFF_MSG  + a] = v;          // msg == mean
                } else {
                    out[OFF_LOG + a] = v;
                }
            }
        }
    }

    // ---- sub barriers: free own weight buffer; publish smean (A -> B) ----
    if (isA) { bar_sync(1, 128); bar_arrive(3, 256); }
    else     { bar_sync(2, 128); }

    // ---- staging 2: phase-3 weights (per sub) ----
    {
        const float* w3src = isA ? add_w : gain_w;
        #pragma unroll
        for (int k = 0; k < 16; k++) {
            int c   = u + k * 128;
            int row = c >> 4;
            int col = c & 15;
            cpa16(WB + row * W3S + col * 4,
                  w3src + ((ull)e * L_ + row) * M_ + col * 4);
        }
    }
    cp_commit();
    cp_wait0();
    if (isA) { bar_sync(1, 128); }
    else     { bar_sync(2, 128); bar_sync(3, 256); }  // wait smean from SubA

    // ---- phase 3: 4 rows/thread (lp+32r), 4 batches/thread (bq3+4i) ----
    {
        const int lp  = u >> 2;             // 0..31 (quad-shared -> bcast weights)
        const int bq3 = u & 3;              // 0..3

        ull acc[4][4];
        #pragma unroll
        for (int r = 0; r < 4; r++)
            #pragma unroll
            for (int i = 0; i < 4; i++) acc[r][i] = 0ull;

        #pragma unroll 2
        for (int c = 0; c < 8; c++) {       // 8 m per chunk
            const int m0 = c * 8;
            ulonglong2 wa[4], wb[4];
            #pragma unroll
            for (int r = 0; r < 4; r++) {
                const float* wr = WB + (lp + 32 * r) * W3S + m0;
                wa[r] = *reinterpret_cast<const ulonglong2*>(wr);
                wb[r] = *reinterpret_cast<const ulonglong2*>(wr + 4);
            }
            #pragma unroll
            for (int i = 0; i < 4; i++) {
                const int b = bq3 + 4 * i;
                const float* mr = smean + b * SMS + m0;
                ulonglong2 xa = *reinterpret_cast<const ulonglong2*>(mr);
                ulonglong2 xb = *reinterpret_cast<const ulonglong2*>(mr + 4);
                #pragma unroll
                for (int r = 0; r < 4; r++) {
                    acc[r][i] = fma2(xa.x, wa[r].x, acc[r][i]);
                    acc[r][i] = fma2(xa.y, wa[r].y, acc[r][i]);
                    acc[r][i] = fma2(xb.x, wb[r].x, acc[r][i]);
                    acc[r][i] = fma2(xb.y, wb[r].y, acc[r][i]);
                }
            }
        }

        float* sres = isA ? sadd : sgain;
        #pragma unroll
        for (int r = 0; r < 4; r++) {
            const int l = lp + 32 * r;
            #pragma unroll
            for (int i = 0; i < 4; i++) {
                const int b = bq3 + 4 * i;
                float lo, hi;
                unpk(acc[r][i], lo, hi);
                sres[b * SAS + l] = lo + hi;
            }
        }
    }
    if (isA) bar_sync(1, 128);
    else     bar_sync(2, 128);

    // ---- phase 4: vectorized scatter-add (each sub reduces its own array) ----
    {
        float* sres = isA ? sadd : sgain;
        const ull offI = isA ? OFF_INC_ADD : OFF_INC_GAIN;
        #pragma unroll
        for (int k = 0; k < 4; k++) {
            int i = u + 128 * k;
            int b = i >> 5;
            int q = i & 31;
            float4 v = *reinterpret_cast<const float4*>(sres + b * SAS + q * 4);
            float* dst = out + offI + (ull)(b * R_ + t_idx) * L_ + q * 4;
            red_add_v4(dst, v);
        }
    }
}

extern "C" void kernel_launch(void* const* d_in, const int* in_sizes, int n_in,
                              void* d_out, int out_size) {
    const float* source   = (const float*)d_in[0];
    const float* mean_w   = (const float*)d_in[1];
    const float* mean_b   = (const float*)d_in[2];
    const float* logstd_w = (const float*)d_in[3];
    const float* logstd_b = (const float*)d_in[4];
    const float* add_w    = (const float*)d_in[5];
    const float* gain_w   = (const float*)d_in[6];
    float* out = (float*)d_out;

    cudaFuncSetAttribute(edge_kernel, cudaFuncAttributeMaxDynamicSharedMemorySize,
                         SMEM_FLOATS * 4);

    init_kernel<<<256, 256>>>(out);
    edge_kernel<<<E_, 256, SMEM_FLOATS * 4>>>(source, mean_w, mean_b,
                                              logstd_w, logstd_b,
                                              add_w, gain_w, out);
}